// round 15
// baseline (speedup 1.0000x reference)
#include <cuda_runtime.h>
#include <math.h>

#define NN 100000
#define EE 600000

// ---------------- scratch (static device globals; no allocation) ----------------
__device__ __align__(16) float g_q[NN * 128];
__device__ __align__(16) float g_kv[NN * 256];    // interleaved: k row | v row
__device__ __align__(16) float g_skip[NN * 128];
__device__ __align__(16) float g_denom[NN * 2];
__device__ __align__(16) float g_e[(size_t)EE * 128];   // per-edge lin_edge output

// ---------------- f32x2 packed helpers ----------------
__device__ __forceinline__ unsigned long long pk2(float lo, float hi) {
    unsigned long long r;
    asm("mov.b64 %0, {%1, %2};" : "=l"(r) : "f"(lo), "f"(hi));
    return r;
}
__device__ __forceinline__ float2 upk2(unsigned long long v) {
    float2 r;
    asm("mov.b64 {%0, %1}, %2;" : "=f"(r.x), "=f"(r.y) : "l"(v));
    return r;
}
__device__ __forceinline__ void ffma2(unsigned long long& d, unsigned long long a, unsigned long long b) {
    asm("fma.rn.f32x2 %0, %1, %2, %0;" : "+l"(d) : "l"(a), "l"(b));
}
__device__ __forceinline__ void red_add_v4(float* p, float a, float b, float c, float d) {
    asm volatile("red.global.add.v4.f32 [%0], {%1, %2, %3, %4};"
                 :: "l"(p), "f"(a), "f"(b), "f"(c), "f"(d) : "memory");
}

// ---------------- kernel 0: zero accumulators ----------------
__global__ void init_zero_kernel(float4* __restrict__ out4) {
    int i = blockIdx.x * blockDim.x + threadIdx.x;
    if (i < NN * 32) out4[i] = make_float4(0.f, 0.f, 0.f, 0.f);
    if (i < NN * 2) g_denom[i] = 0.0f;
}

// ---------------- kernel 1: node projections q,k,v,skip (f32x2) ----------------
__global__ __launch_bounds__(512) void proj_kernel(
    const float* __restrict__ x,
    const float* __restrict__ Wq, const float* __restrict__ bq,
    const float* __restrict__ Wk, const float* __restrict__ bk,
    const float* __restrict__ Wv, const float* __restrict__ bv,
    const float* __restrict__ Ws, const float* __restrict__ bs)
{
    __shared__ __align__(16) float xs[128][64];   // [k][r]
    const int node0 = blockIdx.x * 64;
    const int tid = threadIdx.x;

    for (int i = tid; i < 2048; i += 512) {
        int c4 = i >> 6;
        int r  = i & 63;
        int node = node0 + r;
        float4 v = make_float4(0.f, 0.f, 0.f, 0.f);
        if (node < NN) v = reinterpret_cast<const float4*>(x + (size_t)node * 128)[c4];
        xs[c4 * 4 + 0][r] = v.x;
        xs[c4 * 4 + 1][r] = v.y;
        xs[c4 * 4 + 2][r] = v.z;
        xs[c4 * 4 + 3][r] = v.w;
    }
    __syncthreads();

    const int m = tid >> 7;
    const int col = tid & 127;
    const float* W; const float* b; float* outp;
    size_t rstride; int coff;
    if (m == 0)      { W = Wq; b = bq; outp = g_q;    rstride = 128; coff = 0; }
    else if (m == 1) { W = Wk; b = bk; outp = g_kv;   rstride = 256; coff = 0; }
    else if (m == 2) { W = Wv; b = bv; outp = g_kv;   rstride = 256; coff = 128; }
    else             { W = Ws; b = bs; outp = g_skip; rstride = 128; coff = 0; }
    const float bias = b[col];

    unsigned long long acc[32];
#pragma unroll
    for (int j = 0; j < 32; j++) acc[j] = 0ull;

#pragma unroll 4
    for (int k = 0; k < 128; k++) {
        float w = W[k * 128 + col];
        unsigned long long w2 = pk2(w, w);
        const ulonglong2* xr = reinterpret_cast<const ulonglong2*>(&xs[k][0]);
#pragma unroll
        for (int j = 0; j < 16; j++) {
            ulonglong2 a = xr[j];
            ffma2(acc[2 * j],     a.x, w2);
            ffma2(acc[2 * j + 1], a.y, w2);
        }
    }

#pragma unroll
    for (int j = 0; j < 32; j++) {
        float2 v = upk2(acc[j]);
        int n0 = node0 + 2 * j;
        if (n0 < NN)     outp[(size_t)n0 * rstride + coff + col]       = v.x + bias;
        if (n0 + 1 < NN) outp[(size_t)(n0 + 1) * rstride + coff + col] = v.y + bias;
    }
}

// ---------------- kernel 2a: edge GEMM  g_e = [cos-enc | msg] @ We ----------------
// Pure compute: no gathers, no scatter. 512 thr / 16 warps, persistent.
#define ATTR_STRIDE 10

__global__ __launch_bounds__(512) void edge_gemm_kernel(
    const int* __restrict__ ei,
    const float* __restrict__ tarr,
    const float* __restrict__ lastu,
    const float* __restrict__ msg,
    const float* __restrict__ wt,
    const float* __restrict__ bt,
    const float* __restrict__ We)
{
    extern __shared__ __align__(16) float sm[];
    float* We_s = sm;
    float* attr_s = sm + 16384;

    const int tid = threadIdx.x;
    for (int i = tid; i < 4096; i += 512)
        reinterpret_cast<float4*>(We_s)[i] = reinterpret_cast<const float4*>(We)[i];
    __syncthreads();

    const int warp = tid >> 5;
    const int lane = tid & 31;
    float* attr_w = attr_s + warp * (128 * ATTR_STRIDE);

    const float wt0 = wt[lane], wt1 = wt[lane + 32];
    const float bt0 = bt[lane], bt1 = bt[lane + 32];

    const long gw = (long)blockIdx.x * 16 + warp;
    const long nwarps = (long)gridDim.x * 16;

    for (long base = gw * 8; base < EE; base += nwarps * 8) {
        int myE = (int)((EE - base) < 8 ? (EE - base) : 8);

        float rel_r = 0.0f;
        if (lane < myE) {
            long e = base + lane;
            int s = ei[e];                 // src only (dst not needed here)
            rel_r = lastu[s] - tarr[e];
        }

        for (int mm = 0; mm < 8; mm++) {
            if (mm >= myE) break;
            float rel = __shfl_sync(0xffffffffu, rel_r, mm);
            long e = base + mm;
            attr_w[lane * ATTR_STRIDE + mm]        = cosf(fmaf(rel, wt0, bt0));
            attr_w[(lane + 32) * ATTR_STRIDE + mm] = cosf(fmaf(rel, wt1, bt1));
            attr_w[(lane + 64) * ATTR_STRIDE + mm] = msg[e * 64 + lane];
            attr_w[(lane + 96) * ATTR_STRIDE + mm] = msg[e * 64 + lane + 32];
        }
        __syncwarp();

        unsigned long long acc[4][4];
#pragma unroll
        for (int p = 0; p < 4; p++)
#pragma unroll
            for (int c = 0; c < 4; c++) acc[p][c] = 0ull;

        const float4* We4 = reinterpret_cast<const float4*>(We_s);
#pragma unroll 4
        for (int k = 0; k < 128; k++) {
            float4 w = We4[k * 32 + lane];
            unsigned long long wx = pk2(w.x, w.x);
            unsigned long long wy = pk2(w.y, w.y);
            unsigned long long wz = pk2(w.z, w.z);
            unsigned long long ww = pk2(w.w, w.w);
            const unsigned long long* ap =
                reinterpret_cast<const unsigned long long*>(attr_w + k * ATTR_STRIDE);
            unsigned long long a0 = ap[0], a1 = ap[1], a2 = ap[2], a3 = ap[3];
            ffma2(acc[0][0], a0, wx); ffma2(acc[0][1], a0, wy);
            ffma2(acc[0][2], a0, wz); ffma2(acc[0][3], a0, ww);
            ffma2(acc[1][0], a1, wx); ffma2(acc[1][1], a1, wy);
            ffma2(acc[1][2], a1, wz); ffma2(acc[1][3], a1, ww);
            ffma2(acc[2][0], a2, wx); ffma2(acc[2][1], a2, wy);
            ffma2(acc[2][2], a2, wz); ffma2(acc[2][3], a2, ww);
            ffma2(acc[3][0], a3, wx); ffma2(acc[3][1], a3, wy);
            ffma2(acc[3][2], a3, wz); ffma2(acc[3][3], a3, ww);
        }

        // stream results: g_e[e][lane*4..+3]
#pragma unroll
        for (int mm = 0; mm < 8; mm++) {
            if (mm >= myE) break;
            float2 t0 = upk2(acc[mm >> 1][0]);
            float2 t1 = upk2(acc[mm >> 1][1]);
            float2 t2 = upk2(acc[mm >> 1][2]);
            float2 t3 = upk2(acc[mm >> 1][3]);
            float4 o;
            if (mm & 1) o = make_float4(t0.y, t1.y, t2.y, t3.y);
            else        o = make_float4(t0.x, t1.x, t2.x, t3.x);
            reinterpret_cast<float4*>(g_e + (size_t)(base + mm) * 128)[lane] = o;
        }
        __syncwarp();
    }
}

// ---------------- kernel 2b: attention + scatter (high occupancy) ----------------
// 256 thr / 8 warps, 2 edges per warp-iteration, all row loads hoisted (MLP 8).
__global__ __launch_bounds__(256) void scatter_kernel(
    const int* __restrict__ ei,
    float* __restrict__ out)
{
    const int warp = threadIdx.x >> 5;
    const int lane = threadIdx.x & 31;

    const long gw = (long)blockIdx.x * 8 + warp;
    const long nwarps = (long)gridDim.x * 8;

    for (long base = gw * 2; base < EE; base += nwarps * 2) {
        // EE is even and base is even -> always a full pair
        long ea = base, eb = base + 1;
        int sa = ei[ea], da = ei[EE + ea];
        int sb = ei[eb], db = ei[EE + eb];

        // hoisted loads: 8 independent 16B LDGs
        float4 e0 = reinterpret_cast<const float4*>(g_e + (size_t)ea * 128)[lane];
        float4 e1 = reinterpret_cast<const float4*>(g_e + (size_t)eb * 128)[lane];
        float4 q0 = reinterpret_cast<const float4*>(g_q + (size_t)da * 128)[lane];
        float4 q1 = reinterpret_cast<const float4*>(g_q + (size_t)db * 128)[lane];
        const float* kva = g_kv + (size_t)sa * 256;
        const float* kvb = g_kv + (size_t)sb * 256;
        float4 k0 = reinterpret_cast<const float4*>(kva)[lane];
        float4 k1 = reinterpret_cast<const float4*>(kvb)[lane];
        float4 v0 = reinterpret_cast<const float4*>(kva + 128)[lane];
        float4 v1 = reinterpret_cast<const float4*>(kvb + 128)[lane];

        float p0 = q0.x * (k0.x + e0.x) + q0.y * (k0.y + e0.y)
                 + q0.z * (k0.z + e0.z) + q0.w * (k0.w + e0.w);
        float p1 = q1.x * (k1.x + e1.x) + q1.y * (k1.y + e1.y)
                 + q1.z * (k1.z + e1.z) + q1.w * (k1.w + e1.w);

        p0 += __shfl_xor_sync(0xffffffffu, p0, 1);
        p1 += __shfl_xor_sync(0xffffffffu, p1, 1);
        p0 += __shfl_xor_sync(0xffffffffu, p0, 2);
        p1 += __shfl_xor_sync(0xffffffffu, p1, 2);
        p0 += __shfl_xor_sync(0xffffffffu, p0, 4);
        p1 += __shfl_xor_sync(0xffffffffu, p1, 4);
        p0 += __shfl_xor_sync(0xffffffffu, p0, 8);
        p1 += __shfl_xor_sync(0xffffffffu, p1, 8);

        float ex0 = expf(p0 * 0.125f);
        float ex1 = expf(p1 * 0.125f);

        red_add_v4(out + (size_t)da * 128 + lane * 4,
                   ex0 * (v0.x + e0.x), ex0 * (v0.y + e0.y),
                   ex0 * (v0.z + e0.z), ex0 * (v0.w + e0.w));
        red_add_v4(out + (size_t)db * 128 + lane * 4,
                   ex1 * (v1.x + e1.x), ex1 * (v1.y + e1.y),
                   ex1 * (v1.z + e1.z), ex1 * (v1.w + e1.w));

        if (lane == 0) {
            atomicAdd(&g_denom[(size_t)da * 2 + 0], ex0);
            atomicAdd(&g_denom[(size_t)db * 2 + 0], ex1);
        }
        if (lane == 16) {
            atomicAdd(&g_denom[(size_t)da * 2 + 1], ex0);
            atomicAdd(&g_denom[(size_t)db * 2 + 1], ex1);
        }
    }
}

// ---------------- kernel 3: finalize out = acc/denom + skip (float4) ----------------
__global__ void finalize_kernel(float4* __restrict__ out4) {
    int i = blockIdx.x * blockDim.x + threadIdx.x;
    if (i >= NN * 32) return;
    int n = i >> 5;
    int c4 = i & 31;
    int h = c4 >> 4;
    float inv = 1.0f / (g_denom[n * 2 + h] + 1e-16f);
    float4 o = out4[i];
    float4 s = reinterpret_cast<const float4*>(g_skip)[i];
    o.x = o.x * inv + s.x;
    o.y = o.y * inv + s.y;
    o.z = o.z * inv + s.z;
    o.w = o.w * inv + s.w;
    out4[i] = o;
}

// ---------------- launcher ----------------
extern "C" void kernel_launch(void* const* d_in, const int* in_sizes, int n_in,
                              void* d_out, int out_size)
{
    const float* x     = (const float*)d_in[0];
    const float* lastu = (const float*)d_in[1];
    const int*   ei    = (const int*)d_in[2];
    const float* tarr  = (const float*)d_in[3];
    const float* msg   = (const float*)d_in[4];
    const float* wt    = (const float*)d_in[5];
    const float* bt    = (const float*)d_in[6];
    const float* Wq    = (const float*)d_in[7];
    const float* bq    = (const float*)d_in[8];
    const float* Wk    = (const float*)d_in[9];
    const float* bk    = (const float*)d_in[10];
    const float* Wv    = (const float*)d_in[11];
    const float* bv    = (const float*)d_in[12];
    const float* We    = (const float*)d_in[13];
    const float* Ws    = (const float*)d_in[14];
    const float* bs    = (const float*)d_in[15];
    float* out = (float*)d_out;

    init_zero_kernel<<<(NN * 32 + 511) / 512, 512>>>((float4*)out);

    proj_kernel<<<(NN + 63) / 64, 512>>>(x, Wq, bq, Wk, bk, Wv, bv, Ws, bs);

    const int smem = (16384 + 16 * 128 * ATTR_STRIDE) * sizeof(float);  // 147456 B
    cudaFuncSetAttribute(edge_gemm_kernel, cudaFuncAttributeMaxDynamicSharedMemorySize, smem);
    edge_gemm_kernel<<<148, 512, smem>>>(ei, tarr, lastu, msg, wt, bt, We);

    scatter_kernel<<<1184, 256>>>(ei, out);

    finalize_kernel<<<(NN * 32 + 255) / 256, 256>>>((float4*)out);
}